// round 8
// baseline (speedup 1.0000x reference)
#include <cuda_runtime.h>
#include <cuda_fp16.h>
#include <math.h>

#define CG 128
#define CN 64
#define CS 64
#define KK 27
#define EPS 1e-5f

#define MAX_NG 60000
#define MAX_NX 200000

// -------- scratch (device globals, zero-initialized at module load) --------
// Invariant: every kernel_launch invocation leaves d_S, d_colstats, d_zstats
// zeroed for the next invocation (output_kernel resets during S staging).
__device__ __half d_fg[MAX_NG * CN];
__device__ __half d_fs[MAX_NG * CN];
__device__ float d_z[MAX_NG];
__device__ float d_S[MAX_NX * KK];
__device__ float d_colstats[4 * CN];
__device__ float d_zstats[2];

// ---- packed f32x2 helpers (sm_103a FFMA2 via PTX) ----
__device__ __forceinline__ unsigned long long fma2(
    unsigned long long a, unsigned long long b, unsigned long long c) {
    unsigned long long d;
    asm("fma.rn.f32x2 %0, %1, %2, %3;" : "=l"(d) : "l"(a), "l"(b), "l"(c));
    return d;
}
__device__ __forceinline__ unsigned long long dup2(float v) {
    unsigned long long d;
    asm("mov.b64 %0, {%1, %1};" : "=l"(d) : "r"(__float_as_uint(v)));
    return d;
}
union P2 { unsigned long long u; float2 f; };
union W4 { float4 f4; unsigned long long u[2]; };
union H4 { uint4 u; __half2 h[4]; };

// ============ fg = g @ Wg (Ng x 128 @ 128 x 64), FFMA2, fused stats ============
__global__ __launch_bounds__(256) void gemm_g_kernel(
    const float* __restrict__ g, const float* __restrict__ Wg, int Ng) {
    __shared__ float Wsm[CG * CN];
    int t = threadIdx.x;
    for (int i = t; i < CG * CN; i += 256) Wsm[i] = Wg[i];
    __syncthreads();

    const int tr = t >> 3;
    const int c0 = (t & 7) * 8;
    const int r0 = blockIdx.x * 128 + tr * 4;

    unsigned long long acc[4][4];
#pragma unroll
    for (int j = 0; j < 4; j++)
#pragma unroll
        for (int i = 0; i < 4; i++) acc[j][i] = 0ull;

    bool v[4];
    const float4* gp[4];
#pragma unroll
    for (int j = 0; j < 4; j++) {
        v[j] = (r0 + j) < Ng;
        gp[j] = (const float4*)(g + (size_t)(r0 + j) * CG);
    }
    const float4 zero4 = make_float4(0.f, 0.f, 0.f, 0.f);

#pragma unroll 2
    for (int k4 = 0; k4 < CG / 4; k4++) {
        float4 a[4];
#pragma unroll
        for (int j = 0; j < 4; j++) a[j] = v[j] ? __ldcs(&gp[j][k4]) : zero4;
#pragma unroll
        for (int kk = 0; kk < 4; kk++) {
            int k = k4 * 4 + kk;
            W4 w0, w1;
            w0.f4 = *(const float4*)&Wsm[k * CN + c0];
            w1.f4 = *(const float4*)&Wsm[k * CN + c0 + 4];
#pragma unroll
            for (int j = 0; j < 4; j++) {
                unsigned long long av = dup2((&a[j].x)[kk]);
                acc[j][0] = fma2(av, w0.u[0], acc[j][0]);
                acc[j][1] = fma2(av, w0.u[1], acc[j][1]);
                acc[j][2] = fma2(av, w1.u[0], acc[j][2]);
                acc[j][3] = fma2(av, w1.u[1], acc[j][3]);
            }
        }
    }

    float csum[8], csq[8];
#pragma unroll
    for (int i = 0; i < 8; i++) { csum[i] = 0.f; csq[i] = 0.f; }
#pragma unroll
    for (int j = 0; j < 4; j++) {
        float av[8];
#pragma unroll
        for (int i = 0; i < 4; i++) {
            P2 p; p.u = acc[j][i];
            av[2 * i] = p.f.x; av[2 * i + 1] = p.f.y;
        }
        if (r0 + j < Ng) {
            H4 st;
#pragma unroll
            for (int i = 0; i < 4; i++)
                st.h[i] = __floats2half2_rn(av[2 * i], av[2 * i + 1]);
            *(uint4*)&d_fg[(size_t)(r0 + j) * CN + c0] = st.u;
        }
#pragma unroll
        for (int i = 0; i < 8; i++) { csum[i] += av[i]; csq[i] += av[i] * av[i]; }
    }

    __syncthreads();
    float* s_sum = Wsm;
    float* s_sq  = Wsm + 2048;
#pragma unroll
    for (int i = 0; i < 8; i++) {
        s_sum[tr * 64 + c0 + i] = csum[i];
        s_sq[tr * 64 + c0 + i]  = csq[i];
    }
    __syncthreads();
    int col = t & 63, seg = t >> 6;
    float v1 = 0.f, v2 = 0.f;
#pragma unroll
    for (int r = 0; r < 8; r++) {
        v1 += s_sum[(seg * 8 + r) * 64 + col];
        v2 += s_sq[(seg * 8 + r) * 64 + col];
    }
    __syncthreads();
    s_sum[seg * 64 + col] = v1;
    s_sq[seg * 64 + col]  = v2;
    __syncthreads();
    if (t < 64) {
        float a = s_sum[t] + s_sum[64 + t] + s_sum[128 + t] + s_sum[192 + t];
        float b = s_sq[t]  + s_sq[64 + t]  + s_sq[128 + t]  + s_sq[192 + t];
        atomicAdd(&d_colstats[t], a);
        atomicAdd(&d_colstats[64 + t], b);
    }
}

// ============ fs = x[down_idx] @ Ws (Ng x 64 @ 64 x 64), FFMA2, fused stats ============
__global__ __launch_bounds__(256) void gemm_s_kernel(
    const float* __restrict__ x, const int* __restrict__ down_idx,
    const float* __restrict__ Ws, int Ng) {
    __shared__ float Wsm[CS * CN];
    __shared__ float s_red[4096];
    __shared__ int ds[128];
    int t = threadIdx.x;
    for (int i = t; i < CS * CN; i += 256) Wsm[i] = Ws[i];
    int rbase = blockIdx.x * 128;
    if (t < 128) ds[t] = (rbase + t < Ng) ? down_idx[rbase + t] : 0;
    __syncthreads();

    const int tr = t >> 3;
    const int c0 = (t & 7) * 8;
    const int r0 = rbase + tr * 4;

    unsigned long long acc[4][4];
#pragma unroll
    for (int j = 0; j < 4; j++)
#pragma unroll
        for (int i = 0; i < 4; i++) acc[j][i] = 0ull;

    bool v[4];
    const float4* xp[4];
#pragma unroll
    for (int j = 0; j < 4; j++) {
        v[j] = (r0 + j) < Ng;
        xp[j] = (const float4*)(x + (size_t)ds[tr * 4 + j] * CS);
    }
    const float4 zero4 = make_float4(0.f, 0.f, 0.f, 0.f);

#pragma unroll 2
    for (int k4 = 0; k4 < CS / 4; k4++) {
        float4 a[4];
#pragma unroll
        for (int j = 0; j < 4; j++) a[j] = v[j] ? __ldg(&xp[j][k4]) : zero4;
#pragma unroll
        for (int kk = 0; kk < 4; kk++) {
            int k = k4 * 4 + kk;
            W4 w0, w1;
            w0.f4 = *(const float4*)&Wsm[k * CN + c0];
            w1.f4 = *(const float4*)&Wsm[k * CN + c0 + 4];
#pragma unroll
            for (int j = 0; j < 4; j++) {
                unsigned long long av = dup2((&a[j].x)[kk]);
                acc[j][0] = fma2(av, w0.u[0], acc[j][0]);
                acc[j][1] = fma2(av, w0.u[1], acc[j][1]);
                acc[j][2] = fma2(av, w1.u[0], acc[j][2]);
                acc[j][3] = fma2(av, w1.u[1], acc[j][3]);
            }
        }
    }

    float csum[8], csq[8];
#pragma unroll
    for (int i = 0; i < 8; i++) { csum[i] = 0.f; csq[i] = 0.f; }
#pragma unroll
    for (int j = 0; j < 4; j++) {
        float av[8];
#pragma unroll
        for (int i = 0; i < 4; i++) {
            P2 p; p.u = acc[j][i];
            av[2 * i] = p.f.x; av[2 * i + 1] = p.f.y;
        }
        if (r0 + j < Ng) {
            H4 st;
#pragma unroll
            for (int i = 0; i < 4; i++)
                st.h[i] = __floats2half2_rn(av[2 * i], av[2 * i + 1]);
            *(uint4*)&d_fs[(size_t)(r0 + j) * CN + c0] = st.u;
        }
#pragma unroll
        for (int i = 0; i < 8; i++) { csum[i] += av[i]; csq[i] += av[i] * av[i]; }
    }

    float* s_sum = s_red;
    float* s_sq  = s_red + 2048;
#pragma unroll
    for (int i = 0; i < 8; i++) {
        s_sum[tr * 64 + c0 + i] = csum[i];
        s_sq[tr * 64 + c0 + i]  = csq[i];
    }
    __syncthreads();
    int col = t & 63, seg = t >> 6;
    float v1 = 0.f, v2 = 0.f;
#pragma unroll
    for (int r = 0; r < 8; r++) {
        v1 += s_sum[(seg * 8 + r) * 64 + col];
        v2 += s_sq[(seg * 8 + r) * 64 + col];
    }
    __syncthreads();
    s_sum[seg * 64 + col] = v1;
    s_sq[seg * 64 + col]  = v2;
    __syncthreads();
    if (t < 64) {
        float a = s_sum[t] + s_sum[64 + t] + s_sum[128 + t] + s_sum[192 + t];
        float b = s_sq[t]  + s_sq[64 + t]  + s_sq[128 + t]  + s_sq[192 + t];
        atomicAdd(&d_colstats[128 + t], a);
        atomicAdd(&d_colstats[192 + t], b);
    }
}

// -------- fuse: z = (relu(bn_g(fg)) + relu(bn_s(fs))) . Wc; z-stats --------
__global__ __launch_bounds__(256) void fuse_kernel(
    const float* __restrict__ Wc,
    const float* __restrict__ gg, const float* __restrict__ bg,
    const float* __restrict__ gs, const float* __restrict__ bs, int Ng) {
    __shared__ float wc[CN], sgn[CN], bgn[CN], ssn[CN], bsn[CN];
    __shared__ float zs[8][2];
    int t = threadIdx.x;
    if (t < 128) {
        const int c = t & 63;
        const int br = t >> 6;
        float sum = d_colstats[br * 128 + c];
        float sq  = d_colstats[br * 128 + 64 + c];
        const float inv = 1.f / (float)Ng;
        float mu = sum * inv;
        float var = sq * inv - mu * mu;
        float gam = br ? __ldg(&gs[c]) : __ldg(&gg[c]);
        float bet = br ? __ldg(&bs[c]) : __ldg(&bg[c]);
        float sc = gam * rsqrtf(var + EPS);
        if (br == 0) { sgn[c] = sc; bgn[c] = bet - mu * sc; wc[c] = __ldg(&Wc[c]); }
        else         { ssn[c] = sc; bsn[c] = bet - mu * sc; }
    }
    __syncthreads();

    const int wid = t >> 5, lane = t & 31;
    const int rgrp = lane >> 3;
    const int cg = (lane & 7) * 8;
    float bsum = 0.f, bsq = 0.f;

    for (int rowb = (blockIdx.x * 8 + wid) * 8; rowb < Ng; rowb += gridDim.x * 64) {
        int row[2] = { rowb + rgrp, rowb + 4 + rgrp };
        H4 fgv[2], fsv[2];
#pragma unroll
        for (int q = 0; q < 2; q++) {
            if (row[q] < Ng) {
                fgv[q].u = __ldcs((const uint4*)&d_fg[(size_t)row[q] * CN + cg]);
                fsv[q].u = __ldcs((const uint4*)&d_fs[(size_t)row[q] * CN + cg]);
            }
        }
#pragma unroll
        for (int q = 0; q < 2; q++) {
            float part = 0.f;
            if (row[q] < Ng) {
#pragma unroll
                for (int i = 0; i < 4; i++) {
                    float2 f2 = __half22float2(fgv[q].h[i]);
                    float2 s2 = __half22float2(fsv[q].h[i]);
                    int c = cg + 2 * i;
                    float h0 = fmaxf(f2.x * sgn[c] + bgn[c], 0.f) + fmaxf(s2.x * ssn[c] + bsn[c], 0.f);
                    float h1 = fmaxf(f2.y * sgn[c + 1] + bgn[c + 1], 0.f) + fmaxf(s2.y * ssn[c + 1] + bsn[c + 1], 0.f);
                    part += h0 * wc[c] + h1 * wc[c + 1];
                }
            }
#pragma unroll
            for (int o = 4; o > 0; o >>= 1) part += __shfl_xor_sync(0xffffffffu, part, o);
            if ((lane & 7) == 0 && row[q] < Ng) {
                d_z[row[q]] = part;
                bsum += part;
                bsq += part * part;
            }
        }
    }
    bsum += __shfl_down_sync(0xffffffffu, bsum, 16);
    bsum += __shfl_down_sync(0xffffffffu, bsum, 8);
    bsq  += __shfl_down_sync(0xffffffffu, bsq, 16);
    bsq  += __shfl_down_sync(0xffffffffu, bsq, 8);
    if (lane == 0) { zs[wid][0] = bsum; zs[wid][1] = bsq; }
    __syncthreads();
    if (t == 0) {
        float a = 0.f, q = 0.f;
#pragma unroll
        for (int w = 0; w < 8; w++) { a += zs[w][0]; q += zs[w][1]; }
        atomicAdd(&d_zstats[0], a);
        atomicAdd(&d_zstats[1], q);
    }
}

// -------- scatter: gather z, inline BN+sigmoid, scatter into S --------
__global__ void scatter_kernel(const int* __restrict__ pin,
                               const int* __restrict__ pout,
                               const float* __restrict__ gamma_c,
                               const float* __restrict__ beta_c,
                               int P, float invNg) {
    float mu = d_zstats[0] * invNg;
    float var = d_zstats[1] * invNg - mu * mu;
    float rs = rsqrtf(var + EPS) * __ldg(&gamma_c[0]);
    float bc = __ldg(&beta_c[0]) - mu * rs;

    int i4 = (blockIdx.x * blockDim.x + threadIdx.x) * 4;
    int k = blockIdx.y;
    if (i4 + 3 < P) {
        uint4 pi = *(const uint4*)&pin[(size_t)k * P + i4];
        uint4 po = *(const uint4*)&pout[(size_t)k * P + i4];
        float z0 = __ldg(&d_z[pi.x]);
        float z1 = __ldg(&d_z[pi.y]);
        float z2 = __ldg(&d_z[pi.z]);
        float z3 = __ldg(&d_z[pi.w]);
        float a0 = 1.f / (1.f + __expf(-(z0 * rs + bc)));
        float a1 = 1.f / (1.f + __expf(-(z1 * rs + bc)));
        float a2 = 1.f / (1.f + __expf(-(z2 * rs + bc)));
        float a3 = 1.f / (1.f + __expf(-(z3 * rs + bc)));
        atomicAdd(&d_S[(size_t)po.x * KK + k], a0);
        atomicAdd(&d_S[(size_t)po.y * KK + k], a1);
        atomicAdd(&d_S[(size_t)po.z * KK + k], a2);
        atomicAdd(&d_S[(size_t)po.w * KK + k], a3);
    } else {
        for (int i = i4; i < P; i++) {
            float z = __ldg(&d_z[__ldg(&pin[(size_t)k * P + i])]);
            float a = 1.f / (1.f + __expf(-(z * rs + bc)));
            atomicAdd(&d_S[(size_t)__ldg(&pout[(size_t)k * P + i]) * KK + k], a);
        }
    }
}

// -------- out = x * (S @ W_inv + b_inv) --------
// v2: S-tile staged in smem (coalesced, reset in-place), W_inv column pair
// held in registers as packed f32x2, NO shuffles. Thread owns 2 cols; warp
// processes one row per iteration with a single broadcast LDS.128 per 4 k.
__global__ __launch_bounds__(256) void output_kernel(
    const float* __restrict__ x, const float* __restrict__ Winv,
    const float* __restrict__ binv, float* __restrict__ out, int Nx) {
    __shared__ float s_tile[128 * 28];   // 14336 B, padded rows (28th col = 0)
    __shared__ float wsm[KK * CN];       // 6912 B
    __shared__ float bbs[CN];
    const int t = threadIdx.x;

    for (int i = t; i < KK * CN; i += 256) wsm[i] = Winv[i];
    if (t < CN) bbs[t] = binv[t];
    if (blockIdx.x == 0) {               // reset stats scratch for next run
        d_colstats[t] = 0.f;
        if (t < 2) d_zstats[t] = 0.f;
    }
    if (t < 128) s_tile[t * 28 + 27] = 0.f;   // zero pad column (w[27]=0 anyway)

    const int row0 = blockIdx.x * 128;
    const int nrows = min(128, Nx - row0);
    {
        const int total = nrows * KK;
        const size_t base = (size_t)row0 * KK;
        for (int i = t; i < total; i += 256) {
            float v = d_S[base + i];
            s_tile[(i / KK) * 28 + (i % KK)] = v;
            d_S[base + i] = 0.f;         // reset for next invocation
        }
    }
    __syncthreads();

    const int wid = t >> 5, lane = t & 31;
    const int c = lane * 2;

    // hoist this thread's W_inv column pair: 28 packed f32x2 (k=27 zero)
    unsigned long long wreg[28];
#pragma unroll
    for (int k = 0; k < KK; k++)
        wreg[k] = *(const unsigned long long*)&wsm[k * CN + c];
    wreg[27] = 0ull;
    P2 binit;
    binit.f = *(const float2*)&bbs[c];

    for (int lr = wid; lr < nrows; lr += 8) {
        const int row = row0 + lr;
        float2 xv = __ldcs((const float2*)&x[(size_t)row * CS + c]);
        unsigned long long acc = binit.u;
        const float* srow = &s_tile[lr * 28];
#pragma unroll
        for (int kq = 0; kq < 7; kq++) {
            float4 s4 = *(const float4*)&srow[kq * 4];
            acc = fma2(dup2(s4.x), wreg[kq * 4 + 0], acc);
            acc = fma2(dup2(s4.y), wreg[kq * 4 + 1], acc);
            acc = fma2(dup2(s4.z), wreg[kq * 4 + 2], acc);
            acc = fma2(dup2(s4.w), wreg[kq * 4 + 3], acc);
        }
        P2 p; p.u = acc;
        float2 o;
        o.x = xv.x * p.f.x;
        o.y = xv.y * p.f.y;
        __stcs((float2*)&out[(size_t)row * CS + c], o);
    }
}

extern "C" void kernel_launch(void* const* d_in, const int* in_sizes, int n_in,
                              void* d_out, int out_size) {
    const float* g        = (const float*)d_in[0];
    const float* x        = (const float*)d_in[1];
    const int*   down_idx = (const int*)d_in[2];
    const int*   pairs_in = (const int*)d_in[3];
    const int*   pairs_out= (const int*)d_in[4];
    const float* Wg       = (const float*)d_in[5];
    const float* Ws       = (const float*)d_in[6];
    const float* Wc       = (const float*)d_in[7];
    const float* W_inv    = (const float*)d_in[8];
    const float* b_inv    = (const float*)d_in[9];
    const float* gamma_g  = (const float*)d_in[10];
    const float* beta_g   = (const float*)d_in[11];
    const float* gamma_s  = (const float*)d_in[12];
    const float* beta_s   = (const float*)d_in[13];
    const float* gamma_c  = (const float*)d_in[14];
    const float* beta_c   = (const float*)d_in[15];

    int Ng = in_sizes[0] / CG;
    int Nx = in_sizes[1] / CS;
    int KP = in_sizes[3];
    int P  = KP / KK;

    gemm_g_kernel<<<(Ng + 127) / 128, 256>>>(g, Wg, Ng);
    gemm_s_kernel<<<(Ng + 127) / 128, 256>>>(x, down_idx, Ws, Ng);
    fuse_kernel<<<(Ng + 63) / 64, 256>>>(Wc, gamma_g, beta_g, gamma_s, beta_s, Ng);
    dim3 sgrid(((P + 3) / 4 + 255) / 256, KK);
    scatter_kernel<<<sgrid, 256>>>(pairs_in, pairs_out, gamma_c, beta_c, P, 1.f / (float)Ng);
    output_kernel<<<(Nx + 127) / 128, 256>>>(x, W_inv, b_inv, (float*)d_out, Nx);
}

// round 9
// speedup vs baseline: 1.0636x; 1.0636x over previous
#include <cuda_runtime.h>
#include <cuda_fp16.h>
#include <math.h>

#define CG 128
#define CN 64
#define CS 64
#define KK 27
#define EPS 1e-5f

#define MAX_NG 60000
#define MAX_NX 200000

// -------- scratch (device globals, zero-initialized at module load) --------
// Invariant: every kernel_launch invocation leaves d_S, d_colstats, d_zstats
// zeroed for the next invocation (output_kernel resets during S staging).
__device__ __half d_fg[MAX_NG * CN];
__device__ __half d_fs[MAX_NG * CN];
__device__ float d_z[MAX_NG];
__device__ float d_S[MAX_NX * KK];
__device__ float d_colstats[4 * CN];
__device__ float d_zstats[2];

// ---- packed f32x2 helpers (sm_103a FFMA2 via PTX) ----
__device__ __forceinline__ unsigned long long fma2(
    unsigned long long a, unsigned long long b, unsigned long long c) {
    unsigned long long d;
    asm("fma.rn.f32x2 %0, %1, %2, %3;" : "=l"(d) : "l"(a), "l"(b), "l"(c));
    return d;
}
__device__ __forceinline__ unsigned long long dup2(float v) {
    unsigned long long d;
    asm("mov.b64 %0, {%1, %1};" : "=l"(d) : "r"(__float_as_uint(v)));
    return d;
}
union P2 { unsigned long long u; float2 f; };
union W4 { float4 f4; unsigned long long u[2]; };
union H4 { uint4 u; __half2 h[4]; };

// ============ fg = g @ Wg (Ng x 128 @ 128 x 64), FFMA2, fused stats ============
__global__ __launch_bounds__(256) void gemm_g_kernel(
    const float* __restrict__ g, const float* __restrict__ Wg, int Ng) {
    __shared__ float Wsm[CG * CN];
    int t = threadIdx.x;
    for (int i = t; i < CG * CN; i += 256) Wsm[i] = Wg[i];
    __syncthreads();

    const int tr = t >> 3;
    const int c0 = (t & 7) * 8;
    const int r0 = blockIdx.x * 128 + tr * 4;

    unsigned long long acc[4][4];
#pragma unroll
    for (int j = 0; j < 4; j++)
#pragma unroll
        for (int i = 0; i < 4; i++) acc[j][i] = 0ull;

    bool v[4];
    const float4* gp[4];
#pragma unroll
    for (int j = 0; j < 4; j++) {
        v[j] = (r0 + j) < Ng;
        gp[j] = (const float4*)(g + (size_t)(r0 + j) * CG);
    }
    const float4 zero4 = make_float4(0.f, 0.f, 0.f, 0.f);

#pragma unroll 2
    for (int k4 = 0; k4 < CG / 4; k4++) {
        float4 a[4];
#pragma unroll
        for (int j = 0; j < 4; j++) a[j] = v[j] ? __ldcs(&gp[j][k4]) : zero4;
#pragma unroll
        for (int kk = 0; kk < 4; kk++) {
            int k = k4 * 4 + kk;
            W4 w0, w1;
            w0.f4 = *(const float4*)&Wsm[k * CN + c0];
            w1.f4 = *(const float4*)&Wsm[k * CN + c0 + 4];
#pragma unroll
            for (int j = 0; j < 4; j++) {
                unsigned long long av = dup2((&a[j].x)[kk]);
                acc[j][0] = fma2(av, w0.u[0], acc[j][0]);
                acc[j][1] = fma2(av, w0.u[1], acc[j][1]);
                acc[j][2] = fma2(av, w1.u[0], acc[j][2]);
                acc[j][3] = fma2(av, w1.u[1], acc[j][3]);
            }
        }
    }

    float csum[8], csq[8];
#pragma unroll
    for (int i = 0; i < 8; i++) { csum[i] = 0.f; csq[i] = 0.f; }
#pragma unroll
    for (int j = 0; j < 4; j++) {
        float av[8];
#pragma unroll
        for (int i = 0; i < 4; i++) {
            P2 p; p.u = acc[j][i];
            av[2 * i] = p.f.x; av[2 * i + 1] = p.f.y;
        }
        if (r0 + j < Ng) {
            H4 st;
#pragma unroll
            for (int i = 0; i < 4; i++)
                st.h[i] = __floats2half2_rn(av[2 * i], av[2 * i + 1]);
            *(uint4*)&d_fg[(size_t)(r0 + j) * CN + c0] = st.u;
        }
#pragma unroll
        for (int i = 0; i < 8; i++) { csum[i] += av[i]; csq[i] += av[i] * av[i]; }
    }

    __syncthreads();
    float* s_sum = Wsm;
    float* s_sq  = Wsm + 2048;
#pragma unroll
    for (int i = 0; i < 8; i++) {
        s_sum[tr * 64 + c0 + i] = csum[i];
        s_sq[tr * 64 + c0 + i]  = csq[i];
    }
    __syncthreads();
    int col = t & 63, seg = t >> 6;
    float v1 = 0.f, v2 = 0.f;
#pragma unroll
    for (int r = 0; r < 8; r++) {
        v1 += s_sum[(seg * 8 + r) * 64 + col];
        v2 += s_sq[(seg * 8 + r) * 64 + col];
    }
    __syncthreads();
    s_sum[seg * 64 + col] = v1;
    s_sq[seg * 64 + col]  = v2;
    __syncthreads();
    if (t < 64) {
        float a = s_sum[t] + s_sum[64 + t] + s_sum[128 + t] + s_sum[192 + t];
        float b = s_sq[t]  + s_sq[64 + t]  + s_sq[128 + t]  + s_sq[192 + t];
        atomicAdd(&d_colstats[t], a);
        atomicAdd(&d_colstats[64 + t], b);
    }
}

// ============ fs = x[down_idx] @ Ws (Ng x 64 @ 64 x 64), FFMA2, fused stats ============
__global__ __launch_bounds__(256) void gemm_s_kernel(
    const float* __restrict__ x, const int* __restrict__ down_idx,
    const float* __restrict__ Ws, int Ng) {
    __shared__ float Wsm[CS * CN];
    __shared__ float s_red[4096];
    __shared__ int ds[128];
    int t = threadIdx.x;
    for (int i = t; i < CS * CN; i += 256) Wsm[i] = Ws[i];
    int rbase = blockIdx.x * 128;
    if (t < 128) ds[t] = (rbase + t < Ng) ? down_idx[rbase + t] : 0;
    __syncthreads();

    const int tr = t >> 3;
    const int c0 = (t & 7) * 8;
    const int r0 = rbase + tr * 4;

    unsigned long long acc[4][4];
#pragma unroll
    for (int j = 0; j < 4; j++)
#pragma unroll
        for (int i = 0; i < 4; i++) acc[j][i] = 0ull;

    bool v[4];
    const float4* xp[4];
#pragma unroll
    for (int j = 0; j < 4; j++) {
        v[j] = (r0 + j) < Ng;
        xp[j] = (const float4*)(x + (size_t)ds[tr * 4 + j] * CS);
    }
    const float4 zero4 = make_float4(0.f, 0.f, 0.f, 0.f);

#pragma unroll 2
    for (int k4 = 0; k4 < CS / 4; k4++) {
        float4 a[4];
#pragma unroll
        for (int j = 0; j < 4; j++) a[j] = v[j] ? __ldg(&xp[j][k4]) : zero4;
#pragma unroll
        for (int kk = 0; kk < 4; kk++) {
            int k = k4 * 4 + kk;
            W4 w0, w1;
            w0.f4 = *(const float4*)&Wsm[k * CN + c0];
            w1.f4 = *(const float4*)&Wsm[k * CN + c0 + 4];
#pragma unroll
            for (int j = 0; j < 4; j++) {
                unsigned long long av = dup2((&a[j].x)[kk]);
                acc[j][0] = fma2(av, w0.u[0], acc[j][0]);
                acc[j][1] = fma2(av, w0.u[1], acc[j][1]);
                acc[j][2] = fma2(av, w1.u[0], acc[j][2]);
                acc[j][3] = fma2(av, w1.u[1], acc[j][3]);
            }
        }
    }

    float csum[8], csq[8];
#pragma unroll
    for (int i = 0; i < 8; i++) { csum[i] = 0.f; csq[i] = 0.f; }
#pragma unroll
    for (int j = 0; j < 4; j++) {
        float av[8];
#pragma unroll
        for (int i = 0; i < 4; i++) {
            P2 p; p.u = acc[j][i];
            av[2 * i] = p.f.x; av[2 * i + 1] = p.f.y;
        }
        if (r0 + j < Ng) {
            H4 st;
#pragma unroll
            for (int i = 0; i < 4; i++)
                st.h[i] = __floats2half2_rn(av[2 * i], av[2 * i + 1]);
            *(uint4*)&d_fs[(size_t)(r0 + j) * CN + c0] = st.u;
        }
#pragma unroll
        for (int i = 0; i < 8; i++) { csum[i] += av[i]; csq[i] += av[i] * av[i]; }
    }

    float* s_sum = s_red;
    float* s_sq  = s_red + 2048;
#pragma unroll
    for (int i = 0; i < 8; i++) {
        s_sum[tr * 64 + c0 + i] = csum[i];
        s_sq[tr * 64 + c0 + i]  = csq[i];
    }
    __syncthreads();
    int col = t & 63, seg = t >> 6;
    float v1 = 0.f, v2 = 0.f;
#pragma unroll
    for (int r = 0; r < 8; r++) {
        v1 += s_sum[(seg * 8 + r) * 64 + col];
        v2 += s_sq[(seg * 8 + r) * 64 + col];
    }
    __syncthreads();
    s_sum[seg * 64 + col] = v1;
    s_sq[seg * 64 + col]  = v2;
    __syncthreads();
    if (t < 64) {
        float a = s_sum[t] + s_sum[64 + t] + s_sum[128 + t] + s_sum[192 + t];
        float b = s_sq[t]  + s_sq[64 + t]  + s_sq[128 + t]  + s_sq[192 + t];
        atomicAdd(&d_colstats[128 + t], a);
        atomicAdd(&d_colstats[192 + t], b);
    }
}

// -------- fuse: z = (relu(bn_g(fg)) + relu(bn_s(fs))) . Wc; z-stats --------
__global__ __launch_bounds__(256) void fuse_kernel(
    const float* __restrict__ Wc,
    const float* __restrict__ gg, const float* __restrict__ bg,
    const float* __restrict__ gs, const float* __restrict__ bs, int Ng) {
    __shared__ float wc[CN], sgn[CN], bgn[CN], ssn[CN], bsn[CN];
    __shared__ float zs[8][2];
    int t = threadIdx.x;
    if (t < 128) {
        const int c = t & 63;
        const int br = t >> 6;
        float sum = d_colstats[br * 128 + c];
        float sq  = d_colstats[br * 128 + 64 + c];
        const float inv = 1.f / (float)Ng;
        float mu = sum * inv;
        float var = sq * inv - mu * mu;
        float gam = br ? __ldg(&gs[c]) : __ldg(&gg[c]);
        float bet = br ? __ldg(&bs[c]) : __ldg(&bg[c]);
        float sc = gam * rsqrtf(var + EPS);
        if (br == 0) { sgn[c] = sc; bgn[c] = bet - mu * sc; wc[c] = __ldg(&Wc[c]); }
        else         { ssn[c] = sc; bsn[c] = bet - mu * sc; }
    }
    __syncthreads();

    const int wid = t >> 5, lane = t & 31;
    const int rgrp = lane >> 3;
    const int cg = (lane & 7) * 8;
    float bsum = 0.f, bsq = 0.f;

    for (int rowb = (blockIdx.x * 8 + wid) * 8; rowb < Ng; rowb += gridDim.x * 64) {
        int row[2] = { rowb + rgrp, rowb + 4 + rgrp };
        H4 fgv[2], fsv[2];
#pragma unroll
        for (int q = 0; q < 2; q++) {
            if (row[q] < Ng) {
                fgv[q].u = __ldcs((const uint4*)&d_fg[(size_t)row[q] * CN + cg]);
                fsv[q].u = __ldcs((const uint4*)&d_fs[(size_t)row[q] * CN + cg]);
            }
        }
#pragma unroll
        for (int q = 0; q < 2; q++) {
            float part = 0.f;
            if (row[q] < Ng) {
#pragma unroll
                for (int i = 0; i < 4; i++) {
                    float2 f2 = __half22float2(fgv[q].h[i]);
                    float2 s2 = __half22float2(fsv[q].h[i]);
                    int c = cg + 2 * i;
                    float h0 = fmaxf(f2.x * sgn[c] + bgn[c], 0.f) + fmaxf(s2.x * ssn[c] + bsn[c], 0.f);
                    float h1 = fmaxf(f2.y * sgn[c + 1] + bgn[c + 1], 0.f) + fmaxf(s2.y * ssn[c + 1] + bsn[c + 1], 0.f);
                    part += h0 * wc[c] + h1 * wc[c + 1];
                }
            }
#pragma unroll
            for (int o = 4; o > 0; o >>= 1) part += __shfl_xor_sync(0xffffffffu, part, o);
            if ((lane & 7) == 0 && row[q] < Ng) {
                d_z[row[q]] = part;
                bsum += part;
                bsq += part * part;
            }
        }
    }
    bsum += __shfl_down_sync(0xffffffffu, bsum, 16);
    bsum += __shfl_down_sync(0xffffffffu, bsum, 8);
    bsq  += __shfl_down_sync(0xffffffffu, bsq, 16);
    bsq  += __shfl_down_sync(0xffffffffu, bsq, 8);
    if (lane == 0) { zs[wid][0] = bsum; zs[wid][1] = bsq; }
    __syncthreads();
    if (t == 0) {
        float a = 0.f, q = 0.f;
#pragma unroll
        for (int w = 0; w < 8; w++) { a += zs[w][0]; q += zs[w][1]; }
        atomicAdd(&d_zstats[0], a);
        atomicAdd(&d_zstats[1], q);
    }
}

// -------- scatter: gather z, inline BN+sigmoid, scatter into S --------
__global__ void scatter_kernel(const int* __restrict__ pin,
                               const int* __restrict__ pout,
                               const float* __restrict__ gamma_c,
                               const float* __restrict__ beta_c,
                               int P, float invNg) {
    float mu = d_zstats[0] * invNg;
    float var = d_zstats[1] * invNg - mu * mu;
    float rs = rsqrtf(var + EPS) * __ldg(&gamma_c[0]);
    float bc = __ldg(&beta_c[0]) - mu * rs;

    int i4 = (blockIdx.x * blockDim.x + threadIdx.x) * 4;
    int k = blockIdx.y;
    if (i4 + 3 < P) {
        uint4 pi = *(const uint4*)&pin[(size_t)k * P + i4];
        uint4 po = *(const uint4*)&pout[(size_t)k * P + i4];
        float z0 = __ldg(&d_z[pi.x]);
        float z1 = __ldg(&d_z[pi.y]);
        float z2 = __ldg(&d_z[pi.z]);
        float z3 = __ldg(&d_z[pi.w]);
        float a0 = 1.f / (1.f + __expf(-(z0 * rs + bc)));
        float a1 = 1.f / (1.f + __expf(-(z1 * rs + bc)));
        float a2 = 1.f / (1.f + __expf(-(z2 * rs + bc)));
        float a3 = 1.f / (1.f + __expf(-(z3 * rs + bc)));
        atomicAdd(&d_S[(size_t)po.x * KK + k], a0);
        atomicAdd(&d_S[(size_t)po.y * KK + k], a1);
        atomicAdd(&d_S[(size_t)po.z * KK + k], a2);
        atomicAdd(&d_S[(size_t)po.w * KK + k], a3);
    } else {
        for (int i = i4; i < P; i++) {
            float z = __ldg(&d_z[__ldg(&pin[(size_t)k * P + i])]);
            float a = 1.f / (1.f + __expf(-(z * rs + bc)));
            atomicAdd(&d_S[(size_t)__ldg(&pout[(size_t)k * P + i]) * KK + k], a);
        }
    }
}

// -------- out = x * (S @ W_inv + b_inv) --------
// v3: S staged TRANSPOSED in smem (s_tile[k][row], pitch 132 for alignment),
// thread owns one column with its W_inv column pre-duplicated in registers,
// accumulators packed over ROW PAIRS: per k, one broadcast LDS.128 feeds 4
// rows via two independent fma2 chains. No shuffles, no per-k dup movs.
#define SPITCH 132
__global__ __launch_bounds__(256) void output_kernel(
    const float* __restrict__ x, const float* __restrict__ Winv,
    const float* __restrict__ binv, float* __restrict__ out, int Nx) {
    __shared__ float s_tile[KK * SPITCH];   // 14256 B
    const int t = threadIdx.x;

    if (blockIdx.x == 0) {                  // reset stats scratch for next run
        d_colstats[t] = 0.f;
        if (t < 2) d_zstats[t] = 0.f;
    }

    const int row0 = blockIdx.x * 128;
    const int nrows = min(128, Nx - row0);
    if (nrows < 128) {                      // last block: zero-fill tile
        for (int i = t; i < KK * SPITCH; i += 256) s_tile[i] = 0.f;
        __syncthreads();
    }
    {
        const int total = nrows * KK;
        const size_t base = (size_t)row0 * KK;
        for (int i = t; i < total; i += 256) {
            int r = i / KK;
            int k = i - r * KK;
            s_tile[k * SPITCH + r] = d_S[base + i];
            d_S[base + i] = 0.f;            // reset for next invocation
        }
    }

    // per-thread column and W_inv column (duplicated into packed f32x2)
    const int col = t & 63;
    const int team = t >> 6;                // 0..3 row-group teams
    unsigned long long wreg[KK];
#pragma unroll
    for (int k = 0; k < KK; k++) wreg[k] = dup2(__ldg(&Winv[k * CN + col]));
    const unsigned long long binit = dup2(__ldg(&binv[col]));
    __syncthreads();

    const int ngrp = (nrows + 3) >> 2;      // groups of 4 rows
    for (int g = team; g < ngrp; g += 4) {
        const int r0 = g * 4;
        // independent x loads (guarded; nrows is a multiple of 4 here for all
        // real shapes, guards are for safety)
        float xr[4];
#pragma unroll
        for (int j = 0; j < 4; j++)
            xr[j] = (r0 + j < nrows) ? __ldcs(&x[(size_t)(row0 + r0 + j) * CS + col]) : 0.f;

        unsigned long long acc01 = binit, acc23 = binit;
#pragma unroll
        for (int k = 0; k < KK; k++) {
            W4 s;
            s.f4 = *(const float4*)&s_tile[k * SPITCH + r0];  // broadcast LDS.128
            acc01 = fma2(s.u[0], wreg[k], acc01);
            acc23 = fma2(s.u[1], wreg[k], acc23);
        }
        P2 p0, p1;
        p0.u = acc01; p1.u = acc23;
        float ov[4] = { xr[0] * p0.f.x, xr[1] * p0.f.y, xr[2] * p1.f.x, xr[3] * p1.f.y };
#pragma unroll
        for (int j = 0; j < 4; j++)
            if (r0 + j < nrows)
                __stcs(&out[(size_t)(row0 + r0 + j) * CS + col], ov[j]);
    }
}

extern "C" void kernel_launch(void* const* d_in, const int* in_sizes, int n_in,
                              void* d_out, int out_size) {
    const float* g        = (const float*)d_in[0];
    const float* x        = (const float*)d_in[1];
    const int*   down_idx = (const int*)d_in[2];
    const int*   pairs_in = (const int*)d_in[3];
    const int*   pairs_out= (const int*)d_in[4];
    const float* Wg       = (const float*)d_in[5];
    const float* Ws       = (const float*)d_in[6];
    const float* Wc       = (const float*)d_in[7];
    const float* W_inv    = (const float*)d_in[8];
    const float* b_inv    = (const float*)d_in[9];
    const float* gamma_g  = (const float*)d_in[10];
    const float* beta_g   = (const float*)d_in[11];
    const float* gamma_s  = (const float*)d_in[12];
    const float* beta_s   = (const float*)d_in[13];
    const float* gamma_c  = (const float*)d_in[14];
    const float* beta_c   = (const float*)d_in[15];

    int Ng = in_sizes[0] / CG;
    int Nx = in_sizes[1] / CS;
    int KP = in_sizes[3];
    int P  = KP / KK;

    gemm_g_kernel<<<(Ng + 127) / 128, 256>>>(g, Wg, Ng);
    gemm_s_kernel<<<(Ng + 127) / 128, 256>>>(x, down_idx, Ws, Ng);
    fuse_kernel<<<(Ng + 63) / 64, 256>>>(Wc, gamma_g, beta_g, gamma_s, beta_s, Ng);
    dim3 sgrid(((P + 3) / 4 + 255) / 256, KK);
    scatter_kernel<<<sgrid, 256>>>(pairs_in, pairs_out, gamma_c, beta_c, P, 1.f / (float)Ng);
    output_kernel<<<(Nx + 127) / 128, 256>>>(x, W_inv, b_inv, (float*)d_out, Nx);
}